// round 1
// baseline (speedup 1.0000x reference)
#include <cuda_runtime.h>
#include <cuda_bf16.h>

#define DD 128
#define MAXN 50016
#define MAXE 800000

// Scratch (device globals: allocation-free per harness rules)
__device__ float g_h[(size_t)MAXN * DD];    // post-GEMM features
__device__ float g_act[(size_t)MAXN * DD];  // post-aggregation activations
__device__ float g_dinv[MAXN];
__device__ int   g_cnt[MAXN];
__device__ int   g_off[MAXN + 1];
__device__ int   g_cur[MAXN];
__device__ int   g_esrc[MAXE];
__device__ float g_ew[MAXE];

// ---------------------------------------------------------------------------
// Preprocess kernels
// ---------------------------------------------------------------------------

__global__ void zero_cnt_kernel(int* cnt, int n) {
    int i = blockIdx.x * blockDim.x + threadIdx.x;
    if (i < n) cnt[i] = 0;
}

__global__ void count_kernel(const int* __restrict__ dst, int* __restrict__ cnt, int E) {
    int e = blockIdx.x * blockDim.x + threadIdx.x;
    if (e < E) atomicAdd(&cnt[dst[e]], 1);
}

__global__ void dinv_kernel(const int* __restrict__ cnt, float* __restrict__ dinv, int n) {
    int i = blockIdx.x * blockDim.x + threadIdx.x;
    if (i < n) dinv[i] = rsqrtf((float)(cnt[i] + 1));  // +1 self loop
}

// Single-block exclusive scan of cnt -> off (and cursor copy). n <= ~1M fine.
__global__ void scan_kernel(const int* __restrict__ cnt, int* __restrict__ off,
                            int* __restrict__ cur, int n) {
    __shared__ int sm[1024];
    int t = threadIdx.x;
    int chunk = (n + 1023) >> 10;
    int start = t * chunk;
    int end = min(start + chunk, n);
    int s = 0;
    for (int i = start; i < end; ++i) s += cnt[i];
    sm[t] = s;
    __syncthreads();
    // Hillis-Steele inclusive scan
    for (int ofs = 1; ofs < 1024; ofs <<= 1) {
        int add = (t >= ofs) ? sm[t - ofs] : 0;
        __syncthreads();
        sm[t] += add;
        __syncthreads();
    }
    int base = sm[t] - s;  // exclusive prefix for this chunk
    int run = base;
    for (int i = start; i < end; ++i) {
        off[i] = run;
        cur[i] = run;
        run += cnt[i];
    }
    if (t == 0) off[n] = sm[1023];
}

__global__ void fill_kernel(const int* __restrict__ src, const int* __restrict__ dst,
                            const float* __restrict__ dinv, int* __restrict__ cur,
                            int* __restrict__ esrc, float* __restrict__ ew, int E) {
    int e = blockIdx.x * blockDim.x + threadIdx.x;
    if (e >= E) return;
    int s = src[e];
    int d = dst[e];
    int pos = atomicAdd(&cur[d], 1);
    esrc[pos] = s;
    ew[pos] = dinv[s] * dinv[d];
}

// ---------------------------------------------------------------------------
// GEMM: C[n,128] = A[n,128] @ W[128,128], fp32.
// Tile: 64 rows x 128 cols, BK=32, 256 threads, 8x4 register micro-tile.
// ---------------------------------------------------------------------------

__global__ __launch_bounds__(256) void gemm128_kernel(const float* __restrict__ A,
                                                      const float* __restrict__ W,
                                                      float* __restrict__ C, int n) {
    __shared__ float sA[64 * 32];
    __shared__ float sB[32 * 128];
    const int tx = threadIdx.x;
    const int lane = tx & 31;
    const int wrow = (tx >> 5) * 8;
    const int row0 = blockIdx.x * 64;

    float acc[8][4];
#pragma unroll
    for (int i = 0; i < 8; ++i)
#pragma unroll
        for (int j = 0; j < 4; ++j) acc[i][j] = 0.f;

    for (int k0 = 0; k0 < 128; k0 += 32) {
        // Load A tile: 64 rows x 32 cols = 512 float4
#pragma unroll
        for (int i = tx; i < 512; i += 256) {
            int r = i >> 3, cq = i & 7;
            int gr = row0 + r;
            float4 v = make_float4(0.f, 0.f, 0.f, 0.f);
            if (gr < n) v = *(const float4*)(A + (size_t)gr * DD + k0 + cq * 4);
            *(float4*)(sA + r * 32 + cq * 4) = v;
        }
        // Load W chunk: 32 rows x 128 cols = 1024 float4
#pragma unroll
        for (int i = tx; i < 1024; i += 256) {
            int k = i >> 5, cq = i & 31;
            *(float4*)(sB + k * 128 + cq * 4) =
                *(const float4*)(W + (size_t)(k0 + k) * DD + cq * 4);
        }
        __syncthreads();
#pragma unroll
        for (int k = 0; k < 32; ++k) {
            float4 b = *(const float4*)(sB + k * 128 + lane * 4);
#pragma unroll
            for (int i = 0; i < 8; ++i) {
                float a = sA[(wrow + i) * 32 + k];
                acc[i][0] += a * b.x;
                acc[i][1] += a * b.y;
                acc[i][2] += a * b.z;
                acc[i][3] += a * b.w;
            }
        }
        __syncthreads();
    }
#pragma unroll
    for (int i = 0; i < 8; ++i) {
        int gr = row0 + wrow + i;
        if (gr < n)
            *(float4*)(C + (size_t)gr * DD + lane * 4) =
                make_float4(acc[i][0], acc[i][1], acc[i][2], acc[i][3]);
    }
}

// ---------------------------------------------------------------------------
// Aggregation: one warp per destination node.
// out[i] = relu?( dinv[i]^2 * h[i] + sum_e w_e * h[src_e] + bias )
// Each lane owns a float4 (128 floats / 32 lanes). Row gathers are fully
// coalesced (512B contiguous per warp) and L2-resident.
// ---------------------------------------------------------------------------

__global__ __launch_bounds__(256) void agg_kernel(const float* __restrict__ h,
                                                  const float* __restrict__ dinv,
                                                  const int* __restrict__ off,
                                                  const int* __restrict__ esrc,
                                                  const float* __restrict__ ew,
                                                  const float* __restrict__ bias,
                                                  float* __restrict__ out, int n, int do_relu) {
    int warp = (blockIdx.x * blockDim.x + threadIdx.x) >> 5;
    int lane = threadIdx.x & 31;
    if (warp >= n) return;

    const float4* h4 = (const float4*)h;
    float di = dinv[warp];
    float wself = di * di;
    float4 self = h4[(size_t)warp * 32 + lane];
    float4 bb = ((const float4*)bias)[lane];
    float4 acc;
    acc.x = fmaf(wself, self.x, bb.x);
    acc.y = fmaf(wself, self.y, bb.y);
    acc.z = fmaf(wself, self.z, bb.z);
    acc.w = fmaf(wself, self.w, bb.w);

    int e0 = off[warp], e1 = off[warp + 1];
    int e = e0;
    if (e < e1) {
        int s = esrc[e];
        float w = ew[e];
        for (; e + 1 < e1; ++e) {
            int s2 = esrc[e + 1];
            float w2 = ew[e + 1];
            float4 v = h4[(size_t)s * 32 + lane];
            acc.x = fmaf(w, v.x, acc.x);
            acc.y = fmaf(w, v.y, acc.y);
            acc.z = fmaf(w, v.z, acc.z);
            acc.w = fmaf(w, v.w, acc.w);
            s = s2;
            w = w2;
        }
        float4 v = h4[(size_t)s * 32 + lane];
        acc.x = fmaf(w, v.x, acc.x);
        acc.y = fmaf(w, v.y, acc.y);
        acc.z = fmaf(w, v.z, acc.z);
        acc.w = fmaf(w, v.w, acc.w);
    }
    if (do_relu) {
        acc.x = fmaxf(acc.x, 0.f);
        acc.y = fmaxf(acc.y, 0.f);
        acc.z = fmaxf(acc.z, 0.f);
        acc.w = fmaxf(acc.w, 0.f);
    }
    ((float4*)out)[(size_t)warp * 32 + lane] = acc;
}

// ---------------------------------------------------------------------------
// Launch
// ---------------------------------------------------------------------------

extern "C" void kernel_launch(void* const* d_in, const int* in_sizes, int n_in,
                              void* d_out, int out_size) {
    const float* x  = (const float*)d_in[0];
    const int*   ei = (const int*)d_in[1];
    const float* W1 = (const float*)d_in[2];
    const float* b1 = (const float*)d_in[3];
    const float* W2 = (const float*)d_in[4];
    const float* b2 = (const float*)d_in[5];
    const float* W3 = (const float*)d_in[6];
    const float* b3 = (const float*)d_in[7];

    int n = in_sizes[0] / DD;
    int E = in_sizes[1] / 2;
    const int* src = ei;
    const int* dst = ei + E;

    float *h, *act, *dinv, *ew;
    int *cnt, *off, *cur, *esrc;
    cudaGetSymbolAddress((void**)&h, g_h);
    cudaGetSymbolAddress((void**)&act, g_act);
    cudaGetSymbolAddress((void**)&dinv, g_dinv);
    cudaGetSymbolAddress((void**)&cnt, g_cnt);
    cudaGetSymbolAddress((void**)&off, g_off);
    cudaGetSymbolAddress((void**)&cur, g_cur);
    cudaGetSymbolAddress((void**)&esrc, g_esrc);
    cudaGetSymbolAddress((void**)&ew, g_ew);

    float* outp = (float*)d_out;

    int tb = 256;
    // --- preprocess (graph fixed across layers) ---
    zero_cnt_kernel<<<(n + tb - 1) / tb, tb>>>(cnt, n);
    count_kernel<<<(E + tb - 1) / tb, tb>>>(dst, cnt, E);
    dinv_kernel<<<(n + tb - 1) / tb, tb>>>(cnt, dinv, n);
    scan_kernel<<<1, 1024>>>(cnt, off, cur, n);
    fill_kernel<<<(E + tb - 1) / tb, tb>>>(src, dst, dinv, cur, esrc, ew, E);

    int gemm_grid = (n + 63) / 64;
    int agg_grid = (n + 7) / 8;  // 8 warps per block

    // Layer 1
    gemm128_kernel<<<gemm_grid, 256>>>(x, W1, h, n);
    agg_kernel<<<agg_grid, 256>>>(h, dinv, off, esrc, ew, b1, act, n, 1);
    // Layer 2
    gemm128_kernel<<<gemm_grid, 256>>>(act, W2, h, n);
    agg_kernel<<<agg_grid, 256>>>(h, dinv, off, esrc, ew, b2, act, n, 1);
    // Layer 3
    gemm128_kernel<<<gemm_grid, 256>>>(act, W3, h, n);
    agg_kernel<<<agg_grid, 256>>>(h, dinv, off, esrc, ew, b3, outp, n, 0);
}

// round 2
// speedup vs baseline: 1.2972x; 1.2972x over previous
#include <cuda_runtime.h>
#include <cuda_bf16.h>

#define DD 128
#define MAXN 50016
#define MAXE 800000
#define SCAN_CHUNK 2048           // elements per block in scan (256 thr * 8)
#define MAXP ((MAXN + SCAN_CHUNK - 1) / SCAN_CHUNK)

// Scratch (device globals: allocation-free per harness rules)
__device__ float g_h[(size_t)MAXN * DD];    // post-GEMM features
__device__ float g_act[(size_t)MAXN * DD];  // post-aggregation activations
__device__ float g_dinv[MAXN];
__device__ int   g_cnt[MAXN];
__device__ int   g_off[MAXN + 1];
__device__ int   g_cur[MAXN];
__device__ int   g_esrc[MAXE];
__device__ float g_ew[MAXE];
__device__ int   g_partial[MAXP + 1];

// ---------------------------------------------------------------------------
// Preprocess kernels
// ---------------------------------------------------------------------------

__global__ void zero_cnt_kernel(int* cnt, int n) {
    int i = blockIdx.x * blockDim.x + threadIdx.x;
    if (i < n) cnt[i] = 0;
}

__global__ void count_kernel(const int* __restrict__ dst, int* __restrict__ cnt, int E) {
    int e = blockIdx.x * blockDim.x + threadIdx.x;
    if (e < E) atomicAdd(&cnt[dst[e]], 1);
}

// ---- 3-phase multi-block exclusive scan of cnt[0..n) -> off/cur, plus dinv ----

// Phase 1: per-block sums. Block b covers [b*SCAN_CHUNK, ...), 256 threads x 8 elems.
__global__ __launch_bounds__(256) void scan_p1_kernel(const int* __restrict__ cnt,
                                                      int* __restrict__ partial, int n) {
    __shared__ int warp_sums[8];
    int t = threadIdx.x;
    int base = blockIdx.x * SCAN_CHUNK + t * 8;
    int s = 0;
#pragma unroll
    for (int j = 0; j < 8; ++j) {
        int i = base + j;
        if (i < n) s += cnt[i];
    }
    // warp reduce
#pragma unroll
    for (int o = 16; o > 0; o >>= 1) s += __shfl_down_sync(0xffffffffu, s, o);
    if ((t & 31) == 0) warp_sums[t >> 5] = s;
    __syncthreads();
    if (t < 8) {
        int v = warp_sums[t];
#pragma unroll
        for (int o = 4; o > 0; o >>= 1) v += __shfl_down_sync(0xffu, v, o);
        if (t == 0) partial[blockIdx.x] = v;
    }
}

// Phase 2: exclusive scan of np (<=32) partials by one warp.
__global__ void scan_p2_kernel(int* __restrict__ partial, int* __restrict__ off,
                               int np, int n) {
    int t = threadIdx.x;  // 32 threads
    int v = (t < np) ? partial[t] : 0;
    int orig = v;
#pragma unroll
    for (int o = 1; o < 32; o <<= 1) {
        int u = __shfl_up_sync(0xffffffffu, v, o);
        if (t >= o) v += u;
    }
    if (t < np) partial[t] = v - orig;  // exclusive
    if (t == 31) off[n] = v;            // total edge count
}

// Phase 3: per-block exclusive rescan with base from partial; writes off, cur, dinv.
__global__ __launch_bounds__(256) void scan_p3_kernel(const int* __restrict__ cnt,
                                                      const int* __restrict__ partial,
                                                      int* __restrict__ off,
                                                      int* __restrict__ cur,
                                                      float* __restrict__ dinv, int n) {
    __shared__ int tsum[256];
    int t = threadIdx.x;
    int base = blockIdx.x * SCAN_CHUNK + t * 8;
    int c[8];
    int s = 0;
#pragma unroll
    for (int j = 0; j < 8; ++j) {
        int i = base + j;
        c[j] = (i < n) ? cnt[i] : 0;
        s += c[j];
    }
    tsum[t] = s;
    __syncthreads();
    // Hillis-Steele inclusive over 256
#pragma unroll
    for (int o = 1; o < 256; o <<= 1) {
        int add = (t >= o) ? tsum[t - o] : 0;
        __syncthreads();
        tsum[t] += add;
        __syncthreads();
    }
    int run = partial[blockIdx.x] + tsum[t] - s;  // exclusive prefix
#pragma unroll
    for (int j = 0; j < 8; ++j) {
        int i = base + j;
        if (i < n) {
            off[i] = run;
            cur[i] = run;
            dinv[i] = rsqrtf((float)(c[j] + 1));  // +1 self loop
            run += c[j];
        }
    }
}

__global__ void fill_kernel(const int* __restrict__ src, const int* __restrict__ dst,
                            const float* __restrict__ dinv, int* __restrict__ cur,
                            int* __restrict__ esrc, float* __restrict__ ew, int E) {
    int e = blockIdx.x * blockDim.x + threadIdx.x;
    if (e >= E) return;
    int s = src[e];
    int d = dst[e];
    int pos = atomicAdd(&cur[d], 1);
    esrc[pos] = s;
    ew[pos] = dinv[s] * dinv[d];
}

// ---------------------------------------------------------------------------
// GEMM: C[n,128] = A[n,128] @ W[128,128], fp32.
// Tile: 64 rows x 128 cols, BK=32, 256 threads, 8x4 register micro-tile.
// ---------------------------------------------------------------------------

__global__ __launch_bounds__(256) void gemm128_kernel(const float* __restrict__ A,
                                                      const float* __restrict__ W,
                                                      float* __restrict__ C, int n) {
    __shared__ float sA[64 * 32];
    __shared__ float sB[32 * 128];
    const int tx = threadIdx.x;
    const int lane = tx & 31;
    const int wrow = (tx >> 5) * 8;
    const int row0 = blockIdx.x * 64;

    float acc[8][4];
#pragma unroll
    for (int i = 0; i < 8; ++i)
#pragma unroll
        for (int j = 0; j < 4; ++j) acc[i][j] = 0.f;

    for (int k0 = 0; k0 < 128; k0 += 32) {
#pragma unroll
        for (int i = tx; i < 512; i += 256) {
            int r = i >> 3, cq = i & 7;
            int gr = row0 + r;
            float4 v = make_float4(0.f, 0.f, 0.f, 0.f);
            if (gr < n) v = *(const float4*)(A + (size_t)gr * DD + k0 + cq * 4);
            *(float4*)(sA + r * 32 + cq * 4) = v;
        }
#pragma unroll
        for (int i = tx; i < 1024; i += 256) {
            int k = i >> 5, cq = i & 31;
            *(float4*)(sB + k * 128 + cq * 4) =
                *(const float4*)(W + (size_t)(k0 + k) * DD + cq * 4);
        }
        __syncthreads();
#pragma unroll
        for (int k = 0; k < 32; ++k) {
            float4 b = *(const float4*)(sB + k * 128 + lane * 4);
#pragma unroll
            for (int i = 0; i < 8; ++i) {
                float a = sA[(wrow + i) * 32 + k];
                acc[i][0] += a * b.x;
                acc[i][1] += a * b.y;
                acc[i][2] += a * b.z;
                acc[i][3] += a * b.w;
            }
        }
        __syncthreads();
    }
#pragma unroll
    for (int i = 0; i < 8; ++i) {
        int gr = row0 + wrow + i;
        if (gr < n)
            *(float4*)(C + (size_t)gr * DD + lane * 4) =
                make_float4(acc[i][0], acc[i][1], acc[i][2], acc[i][3]);
    }
}

// ---------------------------------------------------------------------------
// Aggregation: one warp per destination node, 2 edges per iteration for MLP.
// out[i] = relu?( dinv[i]^2 * h[i] + sum_e w_e * h[src_e] + bias )
// ---------------------------------------------------------------------------

__global__ __launch_bounds__(256) void agg_kernel(const float* __restrict__ h,
                                                  const float* __restrict__ dinv,
                                                  const int* __restrict__ off,
                                                  const int* __restrict__ esrc,
                                                  const float* __restrict__ ew,
                                                  const float* __restrict__ bias,
                                                  float* __restrict__ out, int n, int do_relu) {
    int warp = (blockIdx.x * blockDim.x + threadIdx.x) >> 5;
    int lane = threadIdx.x & 31;
    if (warp >= n) return;

    const float4* __restrict__ h4 = (const float4*)h;
    float di = dinv[warp];
    float wself = di * di;
    float4 self = h4[(size_t)warp * 32 + lane];
    float4 bb = ((const float4*)bias)[lane];
    float4 acc;
    acc.x = fmaf(wself, self.x, bb.x);
    acc.y = fmaf(wself, self.y, bb.y);
    acc.z = fmaf(wself, self.z, bb.z);
    acc.w = fmaf(wself, self.w, bb.w);

    int e0 = off[warp], e1 = off[warp + 1];
    int e = e0;
    // 2 edges / iter: two independent 512B row gathers in flight
    for (; e + 1 < e1; e += 2) {
        int s0 = __ldg(&esrc[e]);
        int s1 = __ldg(&esrc[e + 1]);
        float w0 = __ldg(&ew[e]);
        float w1 = __ldg(&ew[e + 1]);
        float4 v0 = h4[(size_t)s0 * 32 + lane];
        float4 v1 = h4[(size_t)s1 * 32 + lane];
        acc.x = fmaf(w0, v0.x, acc.x);
        acc.y = fmaf(w0, v0.y, acc.y);
        acc.z = fmaf(w0, v0.z, acc.z);
        acc.w = fmaf(w0, v0.w, acc.w);
        acc.x = fmaf(w1, v1.x, acc.x);
        acc.y = fmaf(w1, v1.y, acc.y);
        acc.z = fmaf(w1, v1.z, acc.z);
        acc.w = fmaf(w1, v1.w, acc.w);
    }
    if (e < e1) {
        int s0 = __ldg(&esrc[e]);
        float w0 = __ldg(&ew[e]);
        float4 v0 = h4[(size_t)s0 * 32 + lane];
        acc.x = fmaf(w0, v0.x, acc.x);
        acc.y = fmaf(w0, v0.y, acc.y);
        acc.z = fmaf(w0, v0.z, acc.z);
        acc.w = fmaf(w0, v0.w, acc.w);
    }
    if (do_relu) {
        acc.x = fmaxf(acc.x, 0.f);
        acc.y = fmaxf(acc.y, 0.f);
        acc.z = fmaxf(acc.z, 0.f);
        acc.w = fmaxf(acc.w, 0.f);
    }
    ((float4*)out)[(size_t)warp * 32 + lane] = acc;
}

// ---------------------------------------------------------------------------
// Launch
// ---------------------------------------------------------------------------

extern "C" void kernel_launch(void* const* d_in, const int* in_sizes, int n_in,
                              void* d_out, int out_size) {
    const float* x  = (const float*)d_in[0];
    const int*   ei = (const int*)d_in[1];
    const float* W1 = (const float*)d_in[2];
    const float* b1 = (const float*)d_in[3];
    const float* W2 = (const float*)d_in[4];
    const float* b2 = (const float*)d_in[5];
    const float* W3 = (const float*)d_in[6];
    const float* b3 = (const float*)d_in[7];

    int n = in_sizes[0] / DD;
    int E = in_sizes[1] / 2;
    const int* src = ei;
    const int* dst = ei + E;

    float *h, *act, *dinv, *ew;
    int *cnt, *off, *cur, *esrc, *partial;
    cudaGetSymbolAddress((void**)&h, g_h);
    cudaGetSymbolAddress((void**)&act, g_act);
    cudaGetSymbolAddress((void**)&dinv, g_dinv);
    cudaGetSymbolAddress((void**)&cnt, g_cnt);
    cudaGetSymbolAddress((void**)&off, g_off);
    cudaGetSymbolAddress((void**)&cur, g_cur);
    cudaGetSymbolAddress((void**)&esrc, g_esrc);
    cudaGetSymbolAddress((void**)&ew, g_ew);
    cudaGetSymbolAddress((void**)&partial, g_partial);

    float* outp = (float*)d_out;

    int tb = 256;
    int np = (n + SCAN_CHUNK - 1) / SCAN_CHUNK;  // <= 25 for n=50000

    // --- preprocess (graph fixed across layers) ---
    zero_cnt_kernel<<<(n + tb - 1) / tb, tb>>>(cnt, n);
    count_kernel<<<(E + tb - 1) / tb, tb>>>(dst, cnt, E);
    scan_p1_kernel<<<np, 256>>>(cnt, partial, n);
    scan_p2_kernel<<<1, 32>>>(partial, off, np, n);
    scan_p3_kernel<<<np, 256>>>(cnt, partial, off, cur, dinv, n);
    fill_kernel<<<(E + tb - 1) / tb, tb>>>(src, dst, dinv, cur, esrc, ew, E);

    int gemm_grid = (n + 63) / 64;
    int agg_grid = (n + 7) / 8;  // 8 warps per block

    // Layer 1
    gemm128_kernel<<<gemm_grid, 256>>>(x, W1, h, n);
    agg_kernel<<<agg_grid, 256>>>(h, dinv, off, esrc, ew, b1, act, n, 1);
    // Layer 2
    gemm128_kernel<<<gemm_grid, 256>>>(act, W2, h, n);
    agg_kernel<<<agg_grid, 256>>>(h, dinv, off, esrc, ew, b2, act, n, 1);
    // Layer 3
    gemm128_kernel<<<gemm_grid, 256>>>(act, W3, h, n);
    agg_kernel<<<agg_grid, 256>>>(h, dinv, off, esrc, ew, b3, outp, n, 0);
}

// round 4
// speedup vs baseline: 1.5644x; 1.2060x over previous
#include <cuda_runtime.h>
#include <cuda_bf16.h>
#include <cstdint>

#define DD 128
#define MAXN 50016
#define MAXE 800000
#define SCAN_CHUNK 2048
#define MAXP ((MAXN + SCAN_CHUNK - 1) / SCAN_CHUNK)

// ---------------- scratch (device globals; allocation-free) ----------------
__device__ __align__(16) float g_h[(size_t)MAXN * DD];           // post-GEMM fp32
__device__ __align__(16) __nv_bfloat16 g_hi[(size_t)MAXN * DD];  // GEMM input hi
__device__ __align__(16) __nv_bfloat16 g_lo[(size_t)MAXN * DD];  // GEMM input lo
__device__ __align__(16) __nv_bfloat16 g_whi[3 * DD * DD];       // W^T hi per layer
__device__ __align__(16) __nv_bfloat16 g_wlo[3 * DD * DD];       // W^T lo per layer
__device__ float g_dinv[MAXN];
__device__ int   g_cnt[MAXN];
__device__ int   g_off[MAXN + 1];
__device__ int   g_cur[MAXN];
__device__ int   g_esrc[MAXE];
__device__ float g_ew[MAXE];
__device__ int   g_partial[MAXP + 1];

// ---------------------------------------------------------------------------
// Preprocess kernels
// ---------------------------------------------------------------------------
__global__ void zero_cnt_kernel(int* cnt, int n) {
    int i = blockIdx.x * blockDim.x + threadIdx.x;
    if (i < n) cnt[i] = 0;
}
__global__ void count_kernel(const int* __restrict__ dst, int* __restrict__ cnt, int E) {
    int e = blockIdx.x * blockDim.x + threadIdx.x;
    if (e < E) atomicAdd(&cnt[dst[e]], 1);
}
__global__ __launch_bounds__(256) void scan_p1_kernel(const int* __restrict__ cnt,
                                                      int* __restrict__ partial, int n) {
    __shared__ int warp_sums[8];
    int t = threadIdx.x;
    int base = blockIdx.x * SCAN_CHUNK + t * 8;
    int s = 0;
#pragma unroll
    for (int j = 0; j < 8; ++j) {
        int i = base + j;
        if (i < n) s += cnt[i];
    }
#pragma unroll
    for (int o = 16; o > 0; o >>= 1) s += __shfl_down_sync(0xffffffffu, s, o);
    if ((t & 31) == 0) warp_sums[t >> 5] = s;
    __syncthreads();
    if (t < 8) {
        int v = warp_sums[t];
#pragma unroll
        for (int o = 4; o > 0; o >>= 1) v += __shfl_down_sync(0xffu, v, o);
        if (t == 0) partial[blockIdx.x] = v;
    }
}
__global__ void scan_p2_kernel(int* __restrict__ partial, int* __restrict__ off,
                               int np, int n) {
    int t = threadIdx.x;
    int v = (t < np) ? partial[t] : 0;
    int orig = v;
#pragma unroll
    for (int o = 1; o < 32; o <<= 1) {
        int u = __shfl_up_sync(0xffffffffu, v, o);
        if (t >= o) v += u;
    }
    if (t < np) partial[t] = v - orig;
    if (t == 31) off[n] = v;
}
__global__ __launch_bounds__(256) void scan_p3_kernel(const int* __restrict__ cnt,
                                                      const int* __restrict__ partial,
                                                      int* __restrict__ off,
                                                      int* __restrict__ cur,
                                                      float* __restrict__ dinv, int n) {
    __shared__ int tsum[256];
    int t = threadIdx.x;
    int base = blockIdx.x * SCAN_CHUNK + t * 8;
    int c[8];
    int s = 0;
#pragma unroll
    for (int j = 0; j < 8; ++j) {
        int i = base + j;
        c[j] = (i < n) ? cnt[i] : 0;
        s += c[j];
    }
    tsum[t] = s;
    __syncthreads();
#pragma unroll
    for (int o = 1; o < 256; o <<= 1) {
        int add = (t >= o) ? tsum[t - o] : 0;
        __syncthreads();
        tsum[t] += add;
        __syncthreads();
    }
    int run = partial[blockIdx.x] + tsum[t] - s;
#pragma unroll
    for (int j = 0; j < 8; ++j) {
        int i = base + j;
        if (i < n) {
            off[i] = run;
            cur[i] = run;
            dinv[i] = rsqrtf((float)(c[j] + 1));
            run += c[j];
        }
    }
}
__global__ void fill_kernel(const int* __restrict__ src, const int* __restrict__ dst,
                            const float* __restrict__ dinv, int* __restrict__ cur,
                            int* __restrict__ esrc, float* __restrict__ ew, int E) {
    int e = blockIdx.x * blockDim.x + threadIdx.x;
    if (e >= E) return;
    int s = src[e];
    int d = dst[e];
    int pos = atomicAdd(&cur[d], 1);
    esrc[pos] = s;
    ew[pos] = dinv[s] * dinv[d];
}

// ---------------------------------------------------------------------------
// fp32 -> (hi, lo) bf16 split helpers
// ---------------------------------------------------------------------------
__device__ __forceinline__ void split_bf16(float f, __nv_bfloat16& h, __nv_bfloat16& l) {
    h = __float2bfloat16(f);
    l = __float2bfloat16(f - __bfloat162float(h));
}

__global__ void convert_x_kernel(const float* __restrict__ x,
                                 __nv_bfloat16* __restrict__ hi,
                                 __nv_bfloat16* __restrict__ lo, int total) {
    int i = blockIdx.x * blockDim.x + threadIdx.x;
    if (i >= total) return;
    float4 v = ((const float4*)x)[i];
    __nv_bfloat16 h0, h1, h2, h3, l0, l1, l2, l3;
    split_bf16(v.x, h0, l0);
    split_bf16(v.y, h1, l1);
    split_bf16(v.z, h2, l2);
    split_bf16(v.w, h3, l3);
    union { __nv_bfloat162 b[2]; uint2 u; } cv;
    cv.b[0] = __halves2bfloat162(h0, h1);
    cv.b[1] = __halves2bfloat162(h2, h3);
    ((uint2*)hi)[i] = cv.u;
    cv.b[0] = __halves2bfloat162(l0, l1);
    cv.b[1] = __halves2bfloat162(l2, l3);
    ((uint2*)lo)[i] = cv.u;
}

// W[128,128] (x@W uses W[k,n]) -> transposed split bf16 Wt[n,k]
__global__ void wsplit_kernel(const float* __restrict__ W,
                              __nv_bfloat16* __restrict__ bhi,
                              __nv_bfloat16* __restrict__ blo) {
    int i = blockIdx.x * blockDim.x + threadIdx.x;  // over 16384
    if (i >= DD * DD) return;
    int nn = i >> 7, kk = i & 127;
    float v = W[kk * DD + nn];
    __nv_bfloat16 h, l;
    split_bf16(v, h, l);
    bhi[i] = h;
    blo[i] = l;
}

// ---------------------------------------------------------------------------
// HMMA split-bf16 GEMM: C[n,128] = (Ahi+Alo)[n,128] @ Wt^T, via mma.sync
// m16n8k16 row.col bf16->f32. Per CTA: 128 rows x 128 cols. 8 warps; warp w
// owns rows [16w,16w+16). B (Wt hi/lo) staged in smem with stride 136 bf16
// (conflict-free: bank = 4*quad + tq).
// ---------------------------------------------------------------------------
#define BSTRIDE_U32 68  // 136 bf16 per row

__device__ __forceinline__ void mma_bf16(float* c, const uint32_t* a, uint32_t b0, uint32_t b1) {
    asm volatile(
        "mma.sync.aligned.m16n8k16.row.col.f32.bf16.bf16.f32 "
        "{%0,%1,%2,%3}, {%4,%5,%6,%7}, {%8,%9}, {%0,%1,%2,%3};"
        : "+f"(c[0]), "+f"(c[1]), "+f"(c[2]), "+f"(c[3])
        : "r"(a[0]), "r"(a[1]), "r"(a[2]), "r"(a[3]), "r"(b0), "r"(b1));
}

__global__ __launch_bounds__(256) void gemm_hmma_kernel(
    const __nv_bfloat16* __restrict__ Ahi, const __nv_bfloat16* __restrict__ Alo,
    const __nv_bfloat16* __restrict__ Whi, const __nv_bfloat16* __restrict__ Wlo,
    float* __restrict__ C, int n) {
    extern __shared__ uint32_t sB[];  // [2][128 * 68] u32
    uint32_t* sBh = sB;
    uint32_t* sBl = sB + 128 * BSTRIDE_U32;

    const int tid = threadIdx.x;
    const int warp = tid >> 5;
    const int lane = tid & 31;
    const int quad = lane >> 2;   // 0..7
    const int tq = lane & 3;      // 0..3
    const int row0 = blockIdx.x * 128;

    // stage Wt hi/lo into smem (128 rows x 64 u32 each)
    const uint32_t* Wh32 = (const uint32_t*)Whi;
    const uint32_t* Wl32 = (const uint32_t*)Wlo;
#pragma unroll
    for (int i = tid; i < 128 * 64; i += 256) {
        int r = i >> 6, kp = i & 63;
        sBh[r * BSTRIDE_U32 + kp] = Wh32[i];
        sBl[r * BSTRIDE_U32 + kp] = Wl32[i];
    }
    __syncthreads();

    const int row_lo = row0 + warp * 16 + quad;
    const int row_hi = row_lo + 8;
    const bool ok_lo = row_lo < n;
    const bool ok_hi = row_hi < n;

    float acc[16][4];
#pragma unroll
    for (int t = 0; t < 16; ++t)
#pragma unroll
        for (int j = 0; j < 4; ++j) acc[t][j] = 0.f;

#pragma unroll
    for (int ks = 0; ks < 8; ++ks) {
        const int k0 = ks * 16;
        uint32_t ah[4], al[4];
        {
            size_t base_lo = (size_t)row_lo * DD + k0 + 2 * tq;
            size_t base_hi = (size_t)row_hi * DD + k0 + 2 * tq;
            ah[0] = ok_lo ? *(const uint32_t*)(Ahi + base_lo) : 0u;
            ah[1] = ok_hi ? *(const uint32_t*)(Ahi + base_hi) : 0u;
            ah[2] = ok_lo ? *(const uint32_t*)(Ahi + base_lo + 8) : 0u;
            ah[3] = ok_hi ? *(const uint32_t*)(Ahi + base_hi + 8) : 0u;
            al[0] = ok_lo ? *(const uint32_t*)(Alo + base_lo) : 0u;
            al[1] = ok_hi ? *(const uint32_t*)(Alo + base_hi) : 0u;
            al[2] = ok_lo ? *(const uint32_t*)(Alo + base_lo + 8) : 0u;
            al[3] = ok_hi ? *(const uint32_t*)(Alo + base_hi + 8) : 0u;
        }
        const int kbase = (k0 >> 1) + tq;  // u32 offset within row
#pragma unroll
        for (int nt = 0; nt < 16; ++nt) {
            int brow = nt * 8 + quad;
            uint32_t bh0 = sBh[brow * BSTRIDE_U32 + kbase];
            uint32_t bh1 = sBh[brow * BSTRIDE_U32 + kbase + 4];
            uint32_t bl0 = sBl[brow * BSTRIDE_U32 + kbase];
            uint32_t bl1 = sBl[brow * BSTRIDE_U32 + kbase + 4];
            mma_bf16(acc[nt], ah, bh0, bh1);   // Ahi * Bhi
            mma_bf16(acc[nt], ah, bl0, bl1);   // Ahi * Blo
            mma_bf16(acc[nt], al, bh0, bh1);   // Alo * Bhi
        }
    }

    // store
#pragma unroll
    for (int nt = 0; nt < 16; ++nt) {
        int col = nt * 8 + 2 * tq;
        if (ok_lo)
            *(float2*)(C + (size_t)row_lo * DD + col) = make_float2(acc[nt][0], acc[nt][1]);
        if (ok_hi)
            *(float2*)(C + (size_t)row_hi * DD + col) = make_float2(acc[nt][2], acc[nt][3]);
    }
}

// ---------------------------------------------------------------------------
// Aggregation: one warp per node. MODE 1: relu + split-bf16 out. MODE 0: fp32.
// ---------------------------------------------------------------------------
template <int MODE>
__global__ __launch_bounds__(256) void agg_kernel(const float* __restrict__ h,
                                                  const float* __restrict__ dinv,
                                                  const int* __restrict__ off,
                                                  const int* __restrict__ esrc,
                                                  const float* __restrict__ ew,
                                                  const float* __restrict__ bias,
                                                  float* __restrict__ out_f,
                                                  __nv_bfloat16* __restrict__ out_hi,
                                                  __nv_bfloat16* __restrict__ out_lo, int n) {
    int node = (blockIdx.x * blockDim.x + threadIdx.x) >> 5;
    int lane = threadIdx.x & 31;
    if (node >= n) return;

    const float4* __restrict__ h4 = (const float4*)h;
    float di = dinv[node];
    float wself = di * di;
    float4 self = h4[(size_t)node * 32 + lane];
    float4 bb = ((const float4*)bias)[lane];
    float4 acc;
    acc.x = fmaf(wself, self.x, bb.x);
    acc.y = fmaf(wself, self.y, bb.y);
    acc.z = fmaf(wself, self.z, bb.z);
    acc.w = fmaf(wself, self.w, bb.w);

    int e0 = off[node], e1 = off[node + 1];
    int e = e0;
    for (; e + 1 < e1; e += 2) {
        int s0 = __ldg(&esrc[e]);
        int s1 = __ldg(&esrc[e + 1]);
        float w0 = __ldg(&ew[e]);
        float w1 = __ldg(&ew[e + 1]);
        float4 v0 = h4[(size_t)s0 * 32 + lane];
        float4 v1 = h4[(size_t)s1 * 32 + lane];
        acc.x = fmaf(w0, v0.x, acc.x);
        acc.y = fmaf(w0, v0.y, acc.y);
        acc.z = fmaf(w0, v0.z, acc.z);
        acc.w = fmaf(w0, v0.w, acc.w);
        acc.x = fmaf(w1, v1.x, acc.x);
        acc.y = fmaf(w1, v1.y, acc.y);
        acc.z = fmaf(w1, v1.z, acc.z);
        acc.w = fmaf(w1, v1.w, acc.w);
    }
    if (e < e1) {
        int s0 = __ldg(&esrc[e]);
        float w0 = __ldg(&ew[e]);
        float4 v0 = h4[(size_t)s0 * 32 + lane];
        acc.x = fmaf(w0, v0.x, acc.x);
        acc.y = fmaf(w0, v0.y, acc.y);
        acc.z = fmaf(w0, v0.z, acc.z);
        acc.w = fmaf(w0, v0.w, acc.w);
    }
    if (MODE == 1) {
        acc.x = fmaxf(acc.x, 0.f);
        acc.y = fmaxf(acc.y, 0.f);
        acc.z = fmaxf(acc.z, 0.f);
        acc.w = fmaxf(acc.w, 0.f);
        __nv_bfloat16 h0, h1, h2, h3, l0, l1, l2, l3;
        split_bf16(acc.x, h0, l0);
        split_bf16(acc.y, h1, l1);
        split_bf16(acc.z, h2, l2);
        split_bf16(acc.w, h3, l3);
        union { __nv_bfloat162 b[2]; uint2 u; } cv;
        cv.b[0] = __halves2bfloat162(h0, h1);
        cv.b[1] = __halves2bfloat162(h2, h3);
        ((uint2*)out_hi)[(size_t)node * 32 + lane] = cv.u;
        cv.b[0] = __halves2bfloat162(l0, l1);
        cv.b[1] = __halves2bfloat162(l2, l3);
        ((uint2*)out_lo)[(size_t)node * 32 + lane] = cv.u;
    } else {
        ((float4*)out_f)[(size_t)node * 32 + lane] = acc;
    }
}

// ---------------------------------------------------------------------------
// Launch
// ---------------------------------------------------------------------------
extern "C" void kernel_launch(void* const* d_in, const int* in_sizes, int n_in,
                              void* d_out, int out_size) {
    const float* x  = (const float*)d_in[0];
    const int*   ei = (const int*)d_in[1];
    const float* W1 = (const float*)d_in[2];
    const float* b1 = (const float*)d_in[3];
    const float* W2 = (const float*)d_in[4];
    const float* b2 = (const float*)d_in[5];
    const float* W3 = (const float*)d_in[6];
    const float* b3 = (const float*)d_in[7];

    int n = in_sizes[0] / DD;
    int E = in_sizes[1] / 2;
    const int* src = ei;
    const int* dst = ei + E;

    float *h, *dinv, *ew;
    __nv_bfloat16 *hi, *lo, *whi, *wlo;
    int *cnt, *off, *cur, *esrc, *partial;
    cudaGetSymbolAddress((void**)&h, g_h);
    cudaGetSymbolAddress((void**)&hi, g_hi);
    cudaGetSymbolAddress((void**)&lo, g_lo);
    cudaGetSymbolAddress((void**)&whi, g_whi);
    cudaGetSymbolAddress((void**)&wlo, g_wlo);
    cudaGetSymbolAddress((void**)&dinv, g_dinv);
    cudaGetSymbolAddress((void**)&cnt, g_cnt);
    cudaGetSymbolAddress((void**)&off, g_off);
    cudaGetSymbolAddress((void**)&cur, g_cur);
    cudaGetSymbolAddress((void**)&esrc, g_esrc);
    cudaGetSymbolAddress((void**)&ew, g_ew);
    cudaGetSymbolAddress((void**)&partial, g_partial);

    float* outp = (float*)d_out;

    const int GEMM_SMEM = 2 * 128 * BSTRIDE_U32 * 4;  // 69,632 B
    cudaFuncSetAttribute(gemm_hmma_kernel, cudaFuncAttributeMaxDynamicSharedMemorySize,
                         GEMM_SMEM);

    int tb = 256;
    int np = (n + SCAN_CHUNK - 1) / SCAN_CHUNK;

    // --- preprocess ---
    zero_cnt_kernel<<<(n + tb - 1) / tb, tb>>>(cnt, n);
    count_kernel<<<(E + tb - 1) / tb, tb>>>(dst, cnt, E);
    scan_p1_kernel<<<np, 256>>>(cnt, partial, n);
    scan_p2_kernel<<<1, 32>>>(partial, off, np, n);
    scan_p3_kernel<<<np, 256>>>(cnt, partial, off, cur, dinv, n);
    fill_kernel<<<(E + tb - 1) / tb, tb>>>(src, dst, dinv, cur, esrc, ew, E);

    // --- weight transpose + split, input split ---
    wsplit_kernel<<<(DD * DD + 255) / 256, 256>>>(W1, whi, wlo);
    wsplit_kernel<<<(DD * DD + 255) / 256, 256>>>(W2, whi + DD * DD, wlo + DD * DD);
    wsplit_kernel<<<(DD * DD + 255) / 256, 256>>>(W3, whi + 2 * DD * DD, wlo + 2 * DD * DD);
    int tot4 = n * (DD / 4);
    convert_x_kernel<<<(tot4 + 255) / 256, 256>>>(x, hi, lo, tot4);

    int gemm_grid = (n + 127) / 128;
    int agg_grid = (n + 7) / 8;

    // Layer 1
    gemm_hmma_kernel<<<gemm_grid, 256, GEMM_SMEM>>>(hi, lo, whi, wlo, h, n);
    agg_kernel<1><<<agg_grid, 256>>>(h, dinv, off, esrc, ew, b1, nullptr, hi, lo, n);
    // Layer 2
    gemm_hmma_kernel<<<gemm_grid, 256, GEMM_SMEM>>>(hi, lo, whi + DD * DD, wlo + DD * DD, h, n);
    agg_kernel<1><<<agg_grid, 256>>>(h, dinv, off, esrc, ew, b2, nullptr, hi, lo, n);
    // Layer 3
    gemm_hmma_kernel<<<gemm_grid, 256, GEMM_SMEM>>>(hi, lo, whi + 2 * DD * DD,
                                                    wlo + 2 * DD * DD, h, n);
    agg_kernel<0><<<agg_grid, 256>>>(h, dinv, off, esrc, ew, b3, outp, nullptr, nullptr, n);
}

// round 5
// speedup vs baseline: 1.7863x; 1.1418x over previous
#include <cuda_runtime.h>
#include <cuda_bf16.h>
#include <cstdint>

#define DD 128
#define MAXN 50016
#define MAXE 800000
#define SCAN_CHUNK 2048
#define MAXP ((MAXN + SCAN_CHUNK - 1) / SCAN_CHUNK)

// ---------------- scratch (device globals; allocation-free) ----------------
__device__ __align__(16) float g_y[(size_t)MAXN * DD];    // post-agg
__device__ __align__(16) float g_act[(size_t)MAXN * DD];  // post-gemm activation
__device__ __align__(16) __nv_bfloat16 g_whi[3 * DD * DD];
__device__ __align__(16) __nv_bfloat16 g_wlo[3 * DD * DD];
__device__ float g_dinv[MAXN];
__device__ int   g_cnt[MAXN];
__device__ int   g_off[MAXN + 1];
__device__ int   g_cur[MAXN];
__device__ int   g_esrc[MAXE];
__device__ float g_ew[MAXE];
__device__ int   g_partial[MAXP + 1];

// ---------------- helpers ----------------
__device__ __forceinline__ void split_bf16(float f, __nv_bfloat16& h, __nv_bfloat16& l) {
    h = __float2bfloat16(f);
    l = __float2bfloat16(f - __bfloat162float(h));
}
__device__ __forceinline__ void split2(float2 f, uint32_t& hu, uint32_t& lu) {
    __nv_bfloat16 h0, l0, h1, l1;
    split_bf16(f.x, h0, l0);
    split_bf16(f.y, h1, l1);
    union { __nv_bfloat162 b; uint32_t u; } c;
    c.b = __halves2bfloat162(h0, h1);
    hu = c.u;
    c.b = __halves2bfloat162(l0, l1);
    lu = c.u;
}

// ---------------------------------------------------------------------------
// init: zero cnt + transpose/split all 3 weight matrices (one launch)
// ---------------------------------------------------------------------------
__global__ __launch_bounds__(256) void init_kernel(int* __restrict__ cnt, int n, int nzb,
                                                   const float* __restrict__ W1,
                                                   const float* __restrict__ W2,
                                                   const float* __restrict__ W3,
                                                   __nv_bfloat16* __restrict__ whi,
                                                   __nv_bfloat16* __restrict__ wlo) {
    if ((int)blockIdx.x < nzb) {
        int i = blockIdx.x * 256 + threadIdx.x;
        if (i < n) cnt[i] = 0;
    } else {
        int i = (blockIdx.x - nzb) * 256 + threadIdx.x;  // 0..49151
        if (i < 3 * DD * DD) {
            int layer = i / (DD * DD);
            int j = i - layer * (DD * DD);
            const float* W = (layer == 0) ? W1 : ((layer == 1) ? W2 : W3);
            int nn = j >> 7, kk = j & 127;
            float v = W[kk * DD + nn];
            __nv_bfloat16 h, l;
            split_bf16(v, h, l);
            whi[i] = h;
            wlo[i] = l;
        }
    }
}

__global__ void count_kernel(const int* __restrict__ dst, int* __restrict__ cnt, int E) {
    int e = blockIdx.x * blockDim.x + threadIdx.x;
    if (e < E) atomicAdd(&cnt[dst[e]], 1);
}

// Phase 1: per-block sums
__global__ __launch_bounds__(256) void scan_p1_kernel(const int* __restrict__ cnt,
                                                      int* __restrict__ partial, int n) {
    __shared__ int warp_sums[8];
    int t = threadIdx.x;
    int base = blockIdx.x * SCAN_CHUNK + t * 8;
    int s = 0;
#pragma unroll
    for (int j = 0; j < 8; ++j) {
        int i = base + j;
        if (i < n) s += cnt[i];
    }
#pragma unroll
    for (int o = 16; o > 0; o >>= 1) s += __shfl_down_sync(0xffffffffu, s, o);
    if ((t & 31) == 0) warp_sums[t >> 5] = s;
    __syncthreads();
    if (t < 8) {
        int v = warp_sums[t];
#pragma unroll
        for (int o = 4; o > 0; o >>= 1) v += __shfl_down_sync(0xffu, v, o);
        if (t == 0) partial[blockIdx.x] = v;
    }
}

// Phase 3 (merged p2): each block scans the <=32 partials in-register, then
// rescans its chunk. Writes off, cur, dinv; block 0 writes off[n]=total.
__global__ __launch_bounds__(256) void scan_p3_kernel(const int* __restrict__ cnt,
                                                      const int* __restrict__ partial,
                                                      int* __restrict__ off,
                                                      int* __restrict__ cur,
                                                      float* __restrict__ dinv, int n, int np) {
    __shared__ int s_base;
    __shared__ int tsum[256];
    int t = threadIdx.x;
    if (t < 32) {
        int v = (t < np) ? partial[t] : 0;
#pragma unroll
        for (int o = 1; o < 32; o <<= 1) {
            int u = __shfl_up_sync(0xffffffffu, v, o);
            if (t >= o) v += u;
        }
        int srcl = (int)blockIdx.x - 1;
        int excl = __shfl_sync(0xffffffffu, v, (srcl < 0) ? 0 : srcl);
        if (t == 0) s_base = (blockIdx.x == 0) ? 0 : excl;
        if (blockIdx.x == 0 && t == 31) off[n] = v;  // total edges
    }
    __syncthreads();
    int base = blockIdx.x * SCAN_CHUNK + t * 8;
    int c[8];
    int s = 0;
#pragma unroll
    for (int j = 0; j < 8; ++j) {
        int i = base + j;
        c[j] = (i < n) ? cnt[i] : 0;
        s += c[j];
    }
    tsum[t] = s;
    __syncthreads();
#pragma unroll
    for (int o = 1; o < 256; o <<= 1) {
        int add = (t >= o) ? tsum[t - o] : 0;
        __syncthreads();
        tsum[t] += add;
        __syncthreads();
    }
    int run = s_base + tsum[t] - s;
#pragma unroll
    for (int j = 0; j < 8; ++j) {
        int i = base + j;
        if (i < n) {
            off[i] = run;
            cur[i] = run;
            dinv[i] = rsqrtf((float)(c[j] + 1));
            run += c[j];
        }
    }
}

__global__ void fill_kernel(const int* __restrict__ src, const int* __restrict__ dst,
                            const float* __restrict__ dinv, int* __restrict__ cur,
                            int* __restrict__ esrc, float* __restrict__ ew, int E) {
    int e = blockIdx.x * blockDim.x + threadIdx.x;
    if (e >= E) return;
    int s = src[e];
    int d = dst[e];
    int pos = atomicAdd(&cur[d], 1);
    esrc[pos] = s;
    ew[pos] = dinv[s] * dinv[d];
}

// ---------------------------------------------------------------------------
// Aggregation (pure): y[i] = dinv[i]^2 * h[i] + sum_e w_e * h[src_e]
// One warp per node, 4-edge unroll.
// ---------------------------------------------------------------------------
__global__ __launch_bounds__(256) void agg_kernel(const float* __restrict__ h,
                                                  const float* __restrict__ dinv,
                                                  const int* __restrict__ off,
                                                  const int* __restrict__ esrc,
                                                  const float* __restrict__ ew,
                                                  float* __restrict__ out, int n) {
    int node = (blockIdx.x * blockDim.x + threadIdx.x) >> 5;
    int lane = threadIdx.x & 31;
    if (node >= n) return;

    const float4* __restrict__ h4 = (const float4*)h;
    float di = dinv[node];
    float wself = di * di;
    float4 self = h4[(size_t)node * 32 + lane];
    float4 acc;
    acc.x = wself * self.x;
    acc.y = wself * self.y;
    acc.z = wself * self.z;
    acc.w = wself * self.w;

    int e = off[node], e1 = off[node + 1];
    for (; e + 3 < e1; e += 4) {
        int s0 = __ldg(&esrc[e]);
        int s1 = __ldg(&esrc[e + 1]);
        int s2 = __ldg(&esrc[e + 2]);
        int s3 = __ldg(&esrc[e + 3]);
        float w0 = __ldg(&ew[e]);
        float w1 = __ldg(&ew[e + 1]);
        float w2 = __ldg(&ew[e + 2]);
        float w3 = __ldg(&ew[e + 3]);
        float4 v0 = h4[(size_t)s0 * 32 + lane];
        float4 v1 = h4[(size_t)s1 * 32 + lane];
        float4 v2 = h4[(size_t)s2 * 32 + lane];
        float4 v3 = h4[(size_t)s3 * 32 + lane];
        acc.x = fmaf(w0, v0.x, acc.x); acc.y = fmaf(w0, v0.y, acc.y);
        acc.z = fmaf(w0, v0.z, acc.z); acc.w = fmaf(w0, v0.w, acc.w);
        acc.x = fmaf(w1, v1.x, acc.x); acc.y = fmaf(w1, v1.y, acc.y);
        acc.z = fmaf(w1, v1.z, acc.z); acc.w = fmaf(w1, v1.w, acc.w);
        acc.x = fmaf(w2, v2.x, acc.x); acc.y = fmaf(w2, v2.y, acc.y);
        acc.z = fmaf(w2, v2.z, acc.z); acc.w = fmaf(w2, v2.w, acc.w);
        acc.x = fmaf(w3, v3.x, acc.x); acc.y = fmaf(w3, v3.y, acc.y);
        acc.z = fmaf(w3, v3.z, acc.z); acc.w = fmaf(w3, v3.w, acc.w);
    }
    for (; e < e1; ++e) {
        int s0 = __ldg(&esrc[e]);
        float w0 = __ldg(&ew[e]);
        float4 v0 = h4[(size_t)s0 * 32 + lane];
        acc.x = fmaf(w0, v0.x, acc.x); acc.y = fmaf(w0, v0.y, acc.y);
        acc.z = fmaf(w0, v0.z, acc.z); acc.w = fmaf(w0, v0.w, acc.w);
    }
    ((float4*)out)[(size_t)node * 32 + lane] = acc;
}

// ---------------------------------------------------------------------------
// HMMA split-bf16 GEMM + fused bias/ReLU epilogue:
// C[n,128] = relu?( A_fp32[n,128] @ Wt^T + b ). A split into bf16 hi/lo in
// registers; 3 MMAs per tile (AhiBhi + AhiBlo + AloBhi).
// ---------------------------------------------------------------------------
#define BSTRIDE_U32 68  // 136 bf16 per row: conflict-free B-frag LDS

__device__ __forceinline__ void mma_bf16(float* c, const uint32_t* a, uint32_t b0, uint32_t b1) {
    asm volatile(
        "mma.sync.aligned.m16n8k16.row.col.f32.bf16.bf16.f32 "
        "{%0,%1,%2,%3}, {%4,%5,%6,%7}, {%8,%9}, {%0,%1,%2,%3};"
        : "+f"(c[0]), "+f"(c[1]), "+f"(c[2]), "+f"(c[3])
        : "r"(a[0]), "r"(a[1]), "r"(a[2]), "r"(a[3]), "r"(b0), "r"(b1));
}

template <int RELU>
__global__ __launch_bounds__(256) void gemm_hmma_kernel(
    const float* __restrict__ A,
    const __nv_bfloat16* __restrict__ Whi, const __nv_bfloat16* __restrict__ Wlo,
    const float* __restrict__ bias, float* __restrict__ C, int n) {
    extern __shared__ uint32_t sB[];  // [2][128 * 68] u32
    uint32_t* sBh = sB;
    uint32_t* sBl = sB + 128 * BSTRIDE_U32;

    const int tid = threadIdx.x;
    const int warp = tid >> 5;
    const int lane = tid & 31;
    const int quad = lane >> 2;
    const int tq = lane & 3;
    const int row0 = blockIdx.x * 128;

    const uint32_t* Wh32 = (const uint32_t*)Whi;
    const uint32_t* Wl32 = (const uint32_t*)Wlo;
#pragma unroll
    for (int i = tid; i < 128 * 64; i += 256) {
        int r = i >> 6, kp = i & 63;
        sBh[r * BSTRIDE_U32 + kp] = Wh32[i];
        sBl[r * BSTRIDE_U32 + kp] = Wl32[i];
    }
    __syncthreads();

    const int row_lo = row0 + warp * 16 + quad;
    const int row_hi = row_lo + 8;
    const bool ok_lo = row_lo < n;
    const bool ok_hi = row_hi < n;

    float acc[16][4];
#pragma unroll
    for (int t = 0; t < 16; ++t)
#pragma unroll
        for (int j = 0; j < 4; ++j) acc[t][j] = 0.f;

#pragma unroll
    for (int ks = 0; ks < 8; ++ks) {
        const int k0 = ks * 16;
        uint32_t ah[4], al[4];
        {
            const float2 z2 = make_float2(0.f, 0.f);
            size_t base_lo = (size_t)row_lo * DD + k0 + 2 * tq;
            size_t base_hi = (size_t)row_hi * DD + k0 + 2 * tq;
            float2 f0 = ok_lo ? *(const float2*)(A + base_lo) : z2;
            float2 f1 = ok_hi ? *(const float2*)(A + base_hi) : z2;
            float2 f2 = ok_lo ? *(const float2*)(A + base_lo + 8) : z2;
            float2 f3 = ok_hi ? *(const float2*)(A + base_hi + 8) : z2;
            split2(f0, ah[0], al[0]);
            split2(f1, ah[1], al[1]);
            split2(f2, ah[2], al[2]);
            split2(f3, ah[3], al[3]);
        }
        const int kbase = (k0 >> 1) + tq;
#pragma unroll
        for (int nt = 0; nt < 16; ++nt) {
            int brow = nt * 8 + quad;
            uint32_t bh0 = sBh[brow * BSTRIDE_U32 + kbase];
            uint32_t bh1 = sBh[brow * BSTRIDE_U32 + kbase + 4];
            uint32_t bl0 = sBl[brow * BSTRIDE_U32 + kbase];
            uint32_t bl1 = sBl[brow * BSTRIDE_U32 + kbase + 4];
            mma_bf16(acc[nt], ah, bh0, bh1);
            mma_bf16(acc[nt], ah, bl0, bl1);
            mma_bf16(acc[nt], al, bh0, bh1);
        }
    }

#pragma unroll
    for (int nt = 0; nt < 16; ++nt) {
        int col = nt * 8 + 2 * tq;
        float2 bv = *(const float2*)(bias + col);
        float c0 = acc[nt][0] + bv.x, c1 = acc[nt][1] + bv.y;
        float c2 = acc[nt][2] + bv.x, c3 = acc[nt][3] + bv.y;
        if (RELU) {
            c0 = fmaxf(c0, 0.f); c1 = fmaxf(c1, 0.f);
            c2 = fmaxf(c2, 0.f); c3 = fmaxf(c3, 0.f);
        }
        if (ok_lo) *(float2*)(C + (size_t)row_lo * DD + col) = make_float2(c0, c1);
        if (ok_hi) *(float2*)(C + (size_t)row_hi * DD + col) = make_float2(c2, c3);
    }
}

// ---------------------------------------------------------------------------
// Launch: out = (Anorm @ act) @ W + b  per layer (associativity reorder)
// ---------------------------------------------------------------------------
extern "C" void kernel_launch(void* const* d_in, const int* in_sizes, int n_in,
                              void* d_out, int out_size) {
    const float* x  = (const float*)d_in[0];
    const int*   ei = (const int*)d_in[1];
    const float* W1 = (const float*)d_in[2];
    const float* b1 = (const float*)d_in[3];
    const float* W2 = (const float*)d_in[4];
    const float* b2 = (const float*)d_in[5];
    const float* W3 = (const float*)d_in[6];
    const float* b3 = (const float*)d_in[7];

    int n = in_sizes[0] / DD;
    int E = in_sizes[1] / 2;
    const int* src = ei;
    const int* dst = ei + E;

    float *y, *act, *dinv, *ew;
    __nv_bfloat16 *whi, *wlo;
    int *cnt, *off, *cur, *esrc, *partial;
    cudaGetSymbolAddress((void**)&y, g_y);
    cudaGetSymbolAddress((void**)&act, g_act);
    cudaGetSymbolAddress((void**)&whi, g_whi);
    cudaGetSymbolAddress((void**)&wlo, g_wlo);
    cudaGetSymbolAddress((void**)&dinv, g_dinv);
    cudaGetSymbolAddress((void**)&cnt, g_cnt);
    cudaGetSymbolAddress((void**)&off, g_off);
    cudaGetSymbolAddress((void**)&cur, g_cur);
    cudaGetSymbolAddress((void**)&esrc, g_esrc);
    cudaGetSymbolAddress((void**)&ew, g_ew);
    cudaGetSymbolAddress((void**)&partial, g_partial);

    float* outp = (float*)d_out;

    const int GEMM_SMEM = 2 * 128 * BSTRIDE_U32 * 4;  // 69,632 B
    cudaFuncSetAttribute(gemm_hmma_kernel<0>, cudaFuncAttributeMaxDynamicSharedMemorySize,
                         GEMM_SMEM);
    cudaFuncSetAttribute(gemm_hmma_kernel<1>, cudaFuncAttributeMaxDynamicSharedMemorySize,
                         GEMM_SMEM);

    int tb = 256;
    int np = (n + SCAN_CHUNK - 1) / SCAN_CHUNK;
    int nzb = (n + 255) / 256;
    int wsb = (3 * DD * DD + 255) / 256;

    // --- preprocess + weight prep (5 launches) ---
    init_kernel<<<nzb + wsb, 256>>>(cnt, n, nzb, W1, W2, W3, whi, wlo);
    count_kernel<<<(E + tb - 1) / tb, tb>>>(dst, cnt, E);
    scan_p1_kernel<<<np, 256>>>(cnt, partial, n);
    scan_p3_kernel<<<np, 256>>>(cnt, partial, off, cur, dinv, n, np);
    fill_kernel<<<(E + tb - 1) / tb, tb>>>(src, dst, dinv, cur, esrc, ew, E);

    int gemm_grid = (n + 127) / 128;
    int agg_grid = (n + 7) / 8;

    // Layer 1: y = Anorm @ x ; act = relu(y @ W1 + b1)
    agg_kernel<<<agg_grid, 256>>>(x, dinv, off, esrc, ew, y, n);
    gemm_hmma_kernel<1><<<gemm_grid, 256, GEMM_SMEM>>>(y, whi, wlo, b1, act, n);
    // Layer 2
    agg_kernel<<<agg_grid, 256>>>(act, dinv, off, esrc, ew, y, n);
    gemm_hmma_kernel<1><<<gemm_grid, 256, GEMM_SMEM>>>(y, whi + DD * DD, wlo + DD * DD, b2,
                                                       act, n);
    // Layer 3 (no relu) -> d_out
    agg_kernel<<<agg_grid, 256>>>(act, dinv, off, esrc, ew, y, n);
    gemm_hmma_kernel<0><<<gemm_grid, 256, GEMM_SMEM>>>(y, whi + 2 * DD * DD,
                                                       wlo + 2 * DD * DD, b3, outp, n);
}